// round 14
// baseline (speedup 1.0000x reference)
#include <cuda_runtime.h>
#include <cuda_fp16.h>
#include <cstdint>

// ============================================================
// Portable-PTX (base sm_103): ldmatrix + mma.sync fp16, single-pass.
// 4 CTAs/SM, M=64/CTA, cp.async B pipeline (4-kstep units).
// Graph aggregation (A-mix) on tensor cores via exact 0/1 P fragments.
// R14: lane-major B-ring repack (LDS.128) + packed gFC table for FC head.
// ============================================================
__device__ __forceinline__ uint32_t smem_u32(const void* p) {
    uint32_t a;
    asm("{ .reg .u64 t; cvta.to.shared.u64 t, %1; cvt.u32.u64 %0, t; }" : "=r"(a) : "l"(p));
    return a;
}
#define LDSM_X4(a0,a1,a2,a3,addr) \
    asm volatile("ldmatrix.sync.aligned.m8n8.x4.shared.b16 {%0,%1,%2,%3}, [%4];" \
        : "=r"(a0), "=r"(a1), "=r"(a2), "=r"(a3) : "r"(addr))
#define LDSM_X4_T(a0,a1,a2,a3,addr) \
    asm volatile("ldmatrix.sync.aligned.m8n8.x4.trans.shared.b16 {%0,%1,%2,%3}, [%4];" \
        : "=r"(a0), "=r"(a1), "=r"(a2), "=r"(a3) : "r"(addr))
#define MMA_F16(c, a, b0, b1) \
    asm volatile("mma.sync.aligned.m16n8k16.row.col.f32.f16.f16.f32 " \
        "{%0,%1,%2,%3}, {%4,%5,%6,%7}, {%8,%9}, {%0,%1,%2,%3};" \
        : "+f"((c)[0]), "+f"((c)[1]), "+f"((c)[2]), "+f"((c)[3]) \
        : "r"((a)[0]), "r"((a)[1]), "r"((a)[2]), "r"((a)[3]), "r"(b0), "r"(b1))
__device__ __forceinline__ void cp16(uint32_t dst, const void* src) {
    asm volatile("cp.async.ca.shared.global [%0], [%1], 16;" :: "r"(dst), "l"(src));
}
#define CP_COMMIT()  asm volatile("cp.async.commit_group;" ::: "memory")
#define CP_WAIT(n)   asm volatile("cp.async.wait_group %0;" :: "n"(n) : "memory")

namespace {
constexpr int LDX  = 136;   // fp16 row stride (272 B -> LDSM conflict-free)
constexpr int ANN  = 12;    // max nnz per A row (layer-1 gmem premix)
constexpr int MROW = 64;    // rows per CTA tile (63 valid = 3 batches)
constexpr int RPC  = 63;
// dynamic smem offsets
constexpr int OFF_XH   = 0;            // [64][136] fp16 = 17408
constexpr int OFF_B    = 17408;        // ring 2 x 16384 = 32768
constexpr int OFF_AW   = 50176;        // [21][12] f32 (A1 only)
constexpr int OFF_AI   = 53200;        // [21][12] u8
constexpr int OFF_ACNT = 53968;        // i32[64]
constexpr int OFF_OAC  = 54224;        // f32[192]
constexpr int OFF_ROWN = 54992;        // u8[64]
constexpr int SMEM_SZ  = 55296;        // x4 CTAs = 216 KB
// fragment bases (1 frag = B for one (kstep, n-tile); 256 B)
constexpr int FR_W1 = 0;      // 16 ks * 16 nt = 256
constexpr int FR_W2 = 256;    //  8 ks * 16 nt = 128
constexpr int FR_W3 = 384;    //  8 ks * 64 nt = 512
constexpr int NFRAG = 896;
constexpr int NPREP = NFRAG + 48 + 16;   // + P-frag builders + gFC builders
} // namespace

// B fragments, LANE-MAJOR within each 16-frag (4 KB) kstep-group:
// byte offset in group = ng*1024 + lane*32 + j*8  -> sweep reads 2x LDS.128.
__device__ __align__(16) uint2 gWB[NFRAG * 32];
// P (mix matrix) A-operand fragments: [L][mtile][ks][lane] (exact 0/1 fp16).
__device__ __align__(16) uint4 gP[3][4][4][32];
// FC head packed weights: [nc][ng][j][quad][8] = {w(cg).xyz,0, w(cg+1).xyz,0}
__device__ __align__(16) float gFC[4][4][4][4][8];

__device__ __forceinline__ uint32_t pack_h2(float x, float y) {
    __half2 h = __floats2half2_rn(x, y);
    return *reinterpret_cast<uint32_t*>(&h);
}

__global__ void prep_frags(const float* __restrict__ W1,
                           const float* __restrict__ W2,
                           const float* __restrict__ W3,
                           const float* __restrict__ A1,
                           const float* __restrict__ A2,
                           const float* __restrict__ A3,
                           const float* __restrict__ fcW) {
    const int id = blockIdx.x, l = threadIdx.x;
    if (id < NFRAG) {
        const float* W; int ld, r, NT;
        if (id < 256)      { W = W1; ld = 128; r = id;       NT = 16; }
        else if (id < 384) { W = W2; ld = 128; r = id - 256; NT = 16; }
        else               { W = W3; ld = 512; r = id - 384; NT = 64; }
        const int nt = r % NT, ks = r / NT;
        const int n  = nt * 8 + (l >> 2);
        const int k0 = ks * 16 + (l & 3) * 2;
        float v[4];
        #pragma unroll
        for (int i = 0; i < 4; ++i)
            v[i] = W[(size_t)(k0 + (i >> 1) * 8 + (i & 1)) * ld + n];
        // lane-major repack within the 16-frag group
        const int glocal = nt & 15;
        const int gfirst = id - glocal;
        gWB[gfirst * 32 + (glocal >> 2) * 128 + l * 4 + (glocal & 3)] =
            make_uint2(pack_h2(v[0], v[1]), pack_h2(v[2], v[3]));
    } else if (id < NFRAG + 48) {
        // P fragments: block-diag mix matrix, m16k16 A-operand layout.
        int id2 = id - NFRAG;
        int L = id2 >> 4, mtile = (id2 >> 2) & 3, ks = id2 & 3;
        const float* A = (L == 0) ? A1 : ((L == 1) ? A2 : A3);
        const int r0 = mtile * 16 + (l >> 2);
        const int c0 = ks * 16 + (l & 3) * 2;
        float v[8];
        #pragma unroll
        for (int i = 0; i < 8; ++i) {
            int rr = r0 + ((i >> 1) & 1) * 8;
            int cc = c0 + (i & 1) + (i >> 2) * 8;
            float p = 0.f;
            if (rr < 63 && cc < 63 && (rr / 21) == (cc / 21))
                p = A[(rr % 21) * 21 + (cc % 21)];
            v[i] = p;
        }
        gP[L][mtile][ks][l] = make_uint4(pack_h2(v[0], v[1]), pack_h2(v[2], v[3]),
                                         pack_h2(v[4], v[5]), pack_h2(v[6], v[7]));
    } else {
        // gFC: packed fcW table
        int t = id - (NFRAG + 48);
        int nc = t >> 2, ng = t & 3;
        int j = l >> 3, q = (l >> 1) & 3, half = l & 1;
        int col = nc * 128 + ng * 32 + j * 8 + q * 2 + half;
        float* dst = &gFC[nc][ng][j][q][half * 4];
        dst[0] = fcW[col * 3 + 0];
        dst[1] = fcW[col * 3 + 1];
        dst[2] = fcW[col * 3 + 2];
        dst[3] = 0.f;
    }
}

__global__ void __launch_bounds__(256, 4)
handnet_mma(const float* __restrict__ x,
            const float* __restrict__ A1,
            const float* __restrict__ b1, const float* __restrict__ b2,
            const float* __restrict__ b3,
            const float* __restrict__ fcb,
            float* __restrict__ x3g, float* __restrict__ outg, int Btot)
{
    extern __shared__ unsigned char sm[];
    __half*  XH   = (__half*)(sm + OFF_XH);
    float*   Aw   = (float*)(sm + OFF_AW);
    uint8_t* Ai   = sm + OFF_AI;
    int*     Acnt = (int*)(sm + OFF_ACNT);
    float*   Oac  = (float*)(sm + OFF_OAC);
    uint8_t* rown = sm + OFF_ROWN;

    const int tid = threadIdx.x, lane = tid & 31, wid = tid >> 5;
    const int mg = wid >> 2, ng = wid & 3;        // 2 m-groups x 4 n-groups
    const int m0base = mg * 32;
    const int arow = m0base + (lane & 7) + ((lane >> 3) & 1) * 8;
    const int kadd = ((lane >> 4) & 1) * 8;
    const uint32_t xh = smem_u32(XH);
    const uint32_t smB = smem_u32(sm + OFF_B);
    const int tmi = lane >> 3, trow = lane & 7;

    const int b0row = blockIdx.x * RPC;
    const int rows_valid = min(RPC, Btot * 21 - b0row);

    // ---- setup: A1 sparse lists (layer-1 gmem premix only) ----
    if (tid < MROW) rown[tid] = (uint8_t)(tid % 21);
    if (tid < 21) {
        int n = tid, c = 0;
        for (int m = 0; m < 21 && c < ANN; ++m) {
            float v = __ldg(A1 + n * 21 + m);
            if (v != 0.f) { Aw[n*ANN + c] = v; Ai[n*ANN + c] = (uint8_t)m; ++c; }
        }
        Acnt[n] = c;
    }
    if (tid < 192) Oac[tid] = 0.f;
    __syncthreads();

    float C[2][4][4];
    #define ZERO_C() { _Pragma("unroll") for (int mt=0;mt<2;++mt) _Pragma("unroll") \
        for (int j=0;j<4;++j) { C[mt][j][0]=0.f;C[mt][j][1]=0.f;C[mt][j][2]=0.f;C[mt][j][3]=0.f; } }

    auto ldBunit = [&](int fb, int fstride, int slot) {
        #pragma unroll
        for (int h = 0; h < 4; ++h) {
            const char* src = (const char*)(gWB + (size_t)(fb + h * fstride) * 32) + tid * 16;
            cp16(smB + (uint32_t)slot * 16384u + (uint32_t)h * 4096u + (uint32_t)tid * 16u, src);
        }
        CP_COMMIT();
    };

    // ---- pipelined single-pass sweep: 8 ksteps = 2 units; 1 barrier/unit ----
    auto sweepK = [&](int fragbase, int fstride) {
        __syncthreads();
        ldBunit(fragbase, fstride, 0);
        #pragma unroll 1
        for (int u = 0; u < 2; ++u) {
            CP_WAIT(0);
            __syncthreads();
            if (u == 0) ldBunit(fragbase + 4 * fstride, fstride, 1);
            #pragma unroll
            for (int k4 = 0; k4 < 4; ++k4) {
                const int ks = u * 4 + k4;
                uint32_t ah[2][4];
                #pragma unroll
                for (int mt = 0; mt < 2; ++mt) {
                    uint32_t off = (uint32_t)(((arow + mt*16) * LDX + ks*16 + kadd) * 2);
                    LDSM_X4(ah[mt][0], ah[mt][1], ah[mt][2], ah[mt][3], xh + off);
                }
                // lane-major: this warp's 4 j-frags are 32 contiguous bytes
                const unsigned char* bp0 = sm + OFF_B + (u & 1) * 16384 + k4 * 4096
                                             + ng * 1024 + lane * 32;
                uint4 q0 = *(const uint4*)bp0;
                uint4 q1 = *(const uint4*)(bp0 + 16);
                MMA_F16(C[0][0], ah[0], q0.x, q0.y);
                MMA_F16(C[1][0], ah[1], q0.x, q0.y);
                MMA_F16(C[0][1], ah[0], q0.z, q0.w);
                MMA_F16(C[1][1], ah[1], q0.z, q0.w);
                MMA_F16(C[0][2], ah[0], q1.x, q1.y);
                MMA_F16(C[1][2], ah[1], q1.x, q1.y);
                MMA_F16(C[0][3], ah[0], q1.z, q1.w);
                MMA_F16(C[1][3], ah[1], q1.z, q1.w);
            }
        }
    };

    // ---- layer-1 pre-mix: X_mixed = A1 @ x gathered from gmem -> fp16 ----
    auto premix_x = [&](int kc) {
        __syncthreads();
        #pragma unroll 1
        for (int idx = tid; idx < MROW * 32; idx += 256) {
            int r = idx >> 5, q = idx & 31;
            float4 s = make_float4(0.f, 0.f, 0.f, 0.f);
            if (r < rows_valid) {
                int n = rown[r];
                const int gbr = b0row + r - n;
                const int base = n * ANN, cnt = Acnt[n];
                for (int e = 0; e < cnt; ++e) {
                    float a = Aw[base + e];
                    const float4 v = __ldg((const float4*)(x + (size_t)(gbr + Ai[base+e]) * 256 + kc*128) + q);
                    s.x = fmaf(a, v.x, s.x); s.y = fmaf(a, v.y, s.y);
                    s.z = fmaf(a, v.z, s.z); s.w = fmaf(a, v.w, s.w);
                }
            }
            *(uint2*)(XH + r*LDX + q*4) = make_uint2(pack_h2(s.x, s.y), pack_h2(s.z, s.w));
        }
        __syncthreads();
    };

    // ---- layers 1/2 epilogue: bias+relu -> XH; then tensor-core mix ----
    auto epi12 = [&](const float* __restrict__ bias, int Lnext) {
        __syncthreads();
        #pragma unroll
        for (int j = 0; j < 4; ++j) {
            int c  = ng*32 + j*8 + (lane&3)*2;
            float2 bb = __ldg((const float2*)(bias + c));
            #pragma unroll
            for (int mt = 0; mt < 2; ++mt) {
                int r0 = m0base + mt*16 + (lane>>2);
                *(uint32_t*)(XH + r0*LDX + c) =
                    pack_h2(fmaxf(C[mt][j][0] + bb.x, 0.f), fmaxf(C[mt][j][1] + bb.y, 0.f));
                *(uint32_t*)(XH + (r0+8)*LDX + c) =
                    pack_h2(fmaxf(C[mt][j][2] + bb.x, 0.f), fmaxf(C[mt][j][3] + bb.y, 0.f));
            }
        }
        __syncthreads();
        ZERO_C();
        #pragma unroll
        for (int ks = 0; ks < 4; ++ks) {
            uint32_t bt[2][4];
            #pragma unroll
            for (int ch = 0; ch < 2; ++ch) {
                uint32_t off = (uint32_t)(((ks*16 + (tmi&1)*8 + trow) * LDX
                                 + ng*32 + ch*16 + (tmi>>1)*8) * 2);
                LDSM_X4_T(bt[ch][0], bt[ch][1], bt[ch][2], bt[ch][3], xh + off);
            }
            #pragma unroll
            for (int mt = 0; mt < 2; ++mt) {
                uint4 p4 = __ldg(&gP[Lnext][mg*2 + mt][ks][lane]);
                uint32_t ap[4] = {p4.x, p4.y, p4.z, p4.w};
                MMA_F16(C[mt][0], ap, bt[0][0], bt[0][1]);
                MMA_F16(C[mt][1], ap, bt[0][2], bt[0][3]);
                MMA_F16(C[mt][2], ap, bt[1][0], bt[1][1]);
                MMA_F16(C[mt][3], ap, bt[1][2], bt[1][3]);
            }
        }
        __syncthreads();
        #pragma unroll
        for (int mt = 0; mt < 2; ++mt)
            #pragma unroll
            for (int j = 0; j < 4; ++j) {
                int c  = ng*32 + j*8 + (lane&3)*2;
                int r0 = m0base + mt*16 + (lane>>2);
                *(uint32_t*)(XH + r0*LDX + c)     = pack_h2(C[mt][j][0], C[mt][j][1]);
                *(uint32_t*)(XH + (r0+8)*LDX + c) = pack_h2(C[mt][j][2], C[mt][j][3]);
            }
    };

    // ================= Layer 1: K=256 (2 pre-mixed chunks) =================
    ZERO_C();
    premix_x(0);
    sweepK(FR_W1,          16);
    premix_x(1);
    sweepK(FR_W1 + 8 * 16, 16);
    epi12(b1, 1);

    // ================= Layer 2: K=128 =================
    ZERO_C();
    sweepK(FR_W2, 16);
    epi12(b2, 2);

    // ================= Layer 3: K=128, N=512 (4 n-chunks), register epi =====
    #pragma unroll 1
    for (int nc = 0; nc < 4; ++nc) {
        ZERO_C();
        sweepK(FR_W3 + nc * 16, 64);
        float facc[12];
        #pragma unroll
        for (int i = 0; i < 12; ++i) facc[i] = 0.f;
        #pragma unroll
        for (int j = 0; j < 4; ++j) {
            int cg = nc*128 + ng*32 + j*8 + (lane&3)*2;
            float2 bb = __ldg((const float2*)(b3 + cg));
            const float4* fp = (const float4*)gFC[nc][ng][j][lane & 3];
            float4 wa = __ldg(fp);       // weights for col cg
            float4 wb = __ldg(fp + 1);   // weights for col cg+1
            #pragma unroll
            for (int mt = 0; mt < 2; ++mt) {
                int r0 = m0base + mt*16 + (lane>>2);
                bool ok0 = (r0     < rows_valid);
                bool ok1 = (r0 + 8 < rows_valid);
                float v00 = ok0 ? fmaxf(C[mt][j][0] + bb.x, 0.f) : 0.f;
                float v01 = ok0 ? fmaxf(C[mt][j][1] + bb.y, 0.f) : 0.f;
                float v10 = ok1 ? fmaxf(C[mt][j][2] + bb.x, 0.f) : 0.f;
                float v11 = ok1 ? fmaxf(C[mt][j][3] + bb.y, 0.f) : 0.f;
                if (ok0) *(float2*)(x3g + (size_t)(b0row + r0    )*512 + cg) = make_float2(v00, v01);
                if (ok1) *(float2*)(x3g + (size_t)(b0row + r0 + 8)*512 + cg) = make_float2(v10, v11);
                facc[(mt*2+0)*3+0] += v00*wa.x + v01*wb.x;
                facc[(mt*2+0)*3+1] += v00*wa.y + v01*wb.y;
                facc[(mt*2+0)*3+2] += v00*wa.z + v01*wb.z;
                facc[(mt*2+1)*3+0] += v10*wa.x + v11*wb.x;
                facc[(mt*2+1)*3+1] += v10*wa.y + v11*wb.y;
                facc[(mt*2+1)*3+2] += v10*wa.z + v11*wb.z;
            }
        }
        #pragma unroll
        for (int i = 0; i < 12; ++i) {
            facc[i] += __shfl_xor_sync(0xFFFFFFFF, facc[i], 1);
            facc[i] += __shfl_xor_sync(0xFFFFFFFF, facc[i], 2);
        }
        if ((lane & 3) == 0) {
            #pragma unroll
            for (int mt = 0; mt < 2; ++mt)
                #pragma unroll
                for (int rh = 0; rh < 2; ++rh) {
                    int r = m0base + mt*16 + (lane>>2) + rh*8;
                    if (r < rows_valid) {
                        #pragma unroll
                        for (int jo = 0; jo < 3; ++jo)
                            atomicAdd(&Oac[r*3 + jo], facc[(mt*2+rh)*3 + jo]);
                    }
                }
        }
    }

    // ---- final out = FC + fcb ----
    __syncthreads();
    if (tid < 189) {
        int r = tid / 3, j = tid - 3*r;
        if (r < rows_valid)
            outg[(size_t)(b0row + r)*3 + j] = Oac[tid] + __ldg(fcb + j);
    }
    #undef ZERO_C
}

extern "C" void kernel_launch(void* const* d_in, const int* in_sizes, int n_in,
                              void* d_out, int out_size) {
    const float* x   = (const float*)d_in[0];
    const float* A1  = (const float*)d_in[1];
    const float* A2  = (const float*)d_in[2];
    const float* A3  = (const float*)d_in[3];
    const float* W1  = (const float*)d_in[4];
    const float* b1  = (const float*)d_in[5];
    const float* W2  = (const float*)d_in[6];
    const float* b2  = (const float*)d_in[7];
    const float* W3  = (const float*)d_in[8];
    const float* b3  = (const float*)d_in[9];
    const float* fcW = (const float*)d_in[10];
    const float* fcb = (const float*)d_in[11];

    const int Btot = in_sizes[0] / (21 * 256);
    float* x3g  = (float*)d_out;
    float* outg = x3g + (size_t)Btot * 21 * 512;

    static int attr_done = 0;
    if (!attr_done) {
        cudaFuncSetAttribute(handnet_mma, cudaFuncAttributeMaxDynamicSharedMemorySize, SMEM_SZ);
        attr_done = 1;
    }

    prep_frags<<<NPREP, 32>>>(W1, W2, W3, A1, A2, A3, fcW);
    const int nCTA = (Btot * 21 + RPC - 1) / RPC;
    handnet_mma<<<nCTA, 256, SMEM_SZ>>>(x, A1, b1, b2, b3, fcb,
                                        x3g, outg, Btot);
}

// round 17
// speedup vs baseline: 1.6484x; 1.6484x over previous
#include <cuda_runtime.h>
#include <cuda_fp16.h>
#include <cstdint>

// ============================================================
// Portable-PTX (base sm_103): ldmatrix + mma.sync fp16, single-pass.
// 4 CTAs/SM, M=64/CTA, cp.async B pipeline (4-kstep units).
// Graph aggregation (A-mix) on tensor cores via exact 0/1 P fragments.
// R15: conflict-free lane*16 B repack (2x LDS.128) + packed gFC table.
// ============================================================
__device__ __forceinline__ uint32_t smem_u32(const void* p) {
    uint32_t a;
    asm("{ .reg .u64 t; cvta.to.shared.u64 t, %1; cvt.u32.u64 %0, t; }" : "=r"(a) : "l"(p));
    return a;
}
#define LDSM_X4(a0,a1,a2,a3,addr) \
    asm volatile("ldmatrix.sync.aligned.m8n8.x4.shared.b16 {%0,%1,%2,%3}, [%4];" \
        : "=r"(a0), "=r"(a1), "=r"(a2), "=r"(a3) : "r"(addr))
#define LDSM_X4_T(a0,a1,a2,a3,addr) \
    asm volatile("ldmatrix.sync.aligned.m8n8.x4.trans.shared.b16 {%0,%1,%2,%3}, [%4];" \
        : "=r"(a0), "=r"(a1), "=r"(a2), "=r"(a3) : "r"(addr))
#define MMA_F16(c, a, b0, b1) \
    asm volatile("mma.sync.aligned.m16n8k16.row.col.f32.f16.f16.f32 " \
        "{%0,%1,%2,%3}, {%4,%5,%6,%7}, {%8,%9}, {%0,%1,%2,%3};" \
        : "+f"((c)[0]), "+f"((c)[1]), "+f"((c)[2]), "+f"((c)[3]) \
        : "r"((a)[0]), "r"((a)[1]), "r"((a)[2]), "r"((a)[3]), "r"(b0), "r"(b1))
__device__ __forceinline__ void cp16(uint32_t dst, const void* src) {
    asm volatile("cp.async.ca.shared.global [%0], [%1], 16;" :: "r"(dst), "l"(src));
}
#define CP_COMMIT()  asm volatile("cp.async.commit_group;" ::: "memory")
#define CP_WAIT(n)   asm volatile("cp.async.wait_group %0;" :: "n"(n) : "memory")

namespace {
constexpr int LDX  = 136;   // fp16 row stride (272 B -> LDSM conflict-free)
constexpr int ANN  = 12;    // max nnz per A row (layer-1 gmem premix)
constexpr int MROW = 64;    // rows per CTA tile (63 valid = 3 batches)
constexpr int RPC  = 63;
// dynamic smem offsets
constexpr int OFF_XH   = 0;            // [64][136] fp16 = 17408
constexpr int OFF_B    = 17408;        // ring 2 x 16384 = 32768
constexpr int OFF_AW   = 50176;        // [21][12] f32 (A1 only)
constexpr int OFF_AI   = 53200;        // [21][12] u8
constexpr int OFF_ACNT = 53968;        // i32[64]
constexpr int OFF_OAC  = 54224;        // f32[192]
constexpr int OFF_ROWN = 54992;        // u8[64]
constexpr int SMEM_SZ  = 55296;        // x4 CTAs = 216 KB
// fragment bases (1 frag = B for one (kstep, n-tile); 256 B)
constexpr int FR_W1 = 0;      // 16 ks * 16 nt = 256
constexpr int FR_W2 = 256;    //  8 ks * 16 nt = 128
constexpr int FR_W3 = 384;    //  8 ks * 64 nt = 512
constexpr int NFRAG = 896;
constexpr int NPREP = NFRAG + 48 + 16;   // + P-frag builders + gFC builders
} // namespace

// B fragments, conflict-free lane-major within each 16-frag (4 KB) kstep-group:
// byte offset = ng*1024 + (j>>1)*512 + lane*16 + (j&1)*8
// -> sweep reads 2x LDS.128 at lane*16 stride (conflict-free).
__device__ __align__(16) uint2 gWB[NFRAG * 32];
// P (mix matrix) A-operand fragments: [L][mtile][ks][lane] (exact 0/1 fp16).
__device__ __align__(16) uint4 gP[3][4][4][32];
// FC head packed weights: [nc][ng][j][quad][8] = {w(cg).xyz,0, w(cg+1).xyz,0}
__device__ __align__(16) float gFC[4][4][4][4][8];

__device__ __forceinline__ uint32_t pack_h2(float x, float y) {
    __half2 h = __floats2half2_rn(x, y);
    return *reinterpret_cast<uint32_t*>(&h);
}

__global__ void prep_frags(const float* __restrict__ W1,
                           const float* __restrict__ W2,
                           const float* __restrict__ W3,
                           const float* __restrict__ A1,
                           const float* __restrict__ A2,
                           const float* __restrict__ A3,
                           const float* __restrict__ fcW) {
    const int id = blockIdx.x, l = threadIdx.x;
    if (id < NFRAG) {
        const float* W; int ld, r, NT;
        if (id < 256)      { W = W1; ld = 128; r = id;       NT = 16; }
        else if (id < 384) { W = W2; ld = 128; r = id - 256; NT = 16; }
        else               { W = W3; ld = 512; r = id - 384; NT = 64; }
        const int nt = r % NT, ks = r / NT;
        const int n  = nt * 8 + (l >> 2);
        const int k0 = ks * 16 + (l & 3) * 2;
        float v[4];
        #pragma unroll
        for (int i = 0; i < 4; ++i)
            v[i] = W[(size_t)(k0 + (i >> 1) * 8 + (i & 1)) * ld + n];
        // conflict-free repack: ng block, then j-half block, lane*16 stride
        const int glocal = nt & 15;             // = ng*4 + j
        const int gfirst = id - glocal;
        const int ngg = glocal >> 2, jj = glocal & 3;
        gWB[gfirst * 32 + ngg * 128 + (jj >> 1) * 64 + l * 2 + (jj & 1)] =
            make_uint2(pack_h2(v[0], v[1]), pack_h2(v[2], v[3]));
    } else if (id < NFRAG + 48) {
        // P fragments: block-diag mix matrix, m16k16 A-operand layout.
        int id2 = id - NFRAG;
        int L = id2 >> 4, mtile = (id2 >> 2) & 3, ks = id2 & 3;
        const float* A = (L == 0) ? A1 : ((L == 1) ? A2 : A3);
        const int r0 = mtile * 16 + (l >> 2);
        const int c0 = ks * 16 + (l & 3) * 2;
        float v[8];
        #pragma unroll
        for (int i = 0; i < 8; ++i) {
            int rr = r0 + ((i >> 1) & 1) * 8;
            int cc = c0 + (i & 1) + (i >> 2) * 8;
            float p = 0.f;
            if (rr < 63 && cc < 63 && (rr / 21) == (cc / 21))
                p = A[(rr % 21) * 21 + (cc % 21)];
            v[i] = p;
        }
        gP[L][mtile][ks][l] = make_uint4(pack_h2(v[0], v[1]), pack_h2(v[2], v[3]),
                                         pack_h2(v[4], v[5]), pack_h2(v[6], v[7]));
    } else {
        // gFC: packed fcW table
        int t = id - (NFRAG + 48);
        int nc = t >> 2, ng = t & 3;
        int j = l >> 3, q = (l >> 1) & 3, half = l & 1;
        int col = nc * 128 + ng * 32 + j * 8 + q * 2 + half;
        float* dst = &gFC[nc][ng][j][q][half * 4];
        dst[0] = fcW[col * 3 + 0];
        dst[1] = fcW[col * 3 + 1];
        dst[2] = fcW[col * 3 + 2];
        dst[3] = 0.f;
    }
}

__global__ void __launch_bounds__(256, 4)
handnet_mma(const float* __restrict__ x,
            const float* __restrict__ A1,
            const float* __restrict__ b1, const float* __restrict__ b2,
            const float* __restrict__ b3,
            const float* __restrict__ fcb,
            float* __restrict__ x3g, float* __restrict__ outg, int Btot)
{
    extern __shared__ unsigned char sm[];
    __half*  XH   = (__half*)(sm + OFF_XH);
    float*   Aw   = (float*)(sm + OFF_AW);
    uint8_t* Ai   = sm + OFF_AI;
    int*     Acnt = (int*)(sm + OFF_ACNT);
    float*   Oac  = (float*)(sm + OFF_OAC);
    uint8_t* rown = sm + OFF_ROWN;

    const int tid = threadIdx.x, lane = tid & 31, wid = tid >> 5;
    const int mg = wid >> 2, ng = wid & 3;        // 2 m-groups x 4 n-groups
    const int m0base = mg * 32;
    const int arow = m0base + (lane & 7) + ((lane >> 3) & 1) * 8;
    const int kadd = ((lane >> 4) & 1) * 8;
    const uint32_t xh = smem_u32(XH);
    const uint32_t smB = smem_u32(sm + OFF_B);
    const int tmi = lane >> 3, trow = lane & 7;

    const int b0row = blockIdx.x * RPC;
    const int rows_valid = min(RPC, Btot * 21 - b0row);

    // ---- setup: A1 sparse lists (layer-1 gmem premix only) ----
    if (tid < MROW) rown[tid] = (uint8_t)(tid % 21);
    if (tid < 21) {
        int n = tid, c = 0;
        for (int m = 0; m < 21 && c < ANN; ++m) {
            float v = __ldg(A1 + n * 21 + m);
            if (v != 0.f) { Aw[n*ANN + c] = v; Ai[n*ANN + c] = (uint8_t)m; ++c; }
        }
        Acnt[n] = c;
    }
    if (tid < 192) Oac[tid] = 0.f;
    __syncthreads();

    float C[2][4][4];
    #define ZERO_C() { _Pragma("unroll") for (int mt=0;mt<2;++mt) _Pragma("unroll") \
        for (int j=0;j<4;++j) { C[mt][j][0]=0.f;C[mt][j][1]=0.f;C[mt][j][2]=0.f;C[mt][j][3]=0.f; } }

    auto ldBunit = [&](int fb, int fstride, int slot) {
        #pragma unroll
        for (int h = 0; h < 4; ++h) {
            const char* src = (const char*)(gWB + (size_t)(fb + h * fstride) * 32) + tid * 16;
            cp16(smB + (uint32_t)slot * 16384u + (uint32_t)h * 4096u + (uint32_t)tid * 16u, src);
        }
        CP_COMMIT();
    };

    // ---- pipelined single-pass sweep: 8 ksteps = 2 units; 1 barrier/unit ----
    auto sweepK = [&](int fragbase, int fstride) {
        __syncthreads();
        ldBunit(fragbase, fstride, 0);
        #pragma unroll 1
        for (int u = 0; u < 2; ++u) {
            CP_WAIT(0);
            __syncthreads();
            if (u == 0) ldBunit(fragbase + 4 * fstride, fstride, 1);
            #pragma unroll
            for (int k4 = 0; k4 < 4; ++k4) {
                const int ks = u * 4 + k4;
                uint32_t ah[2][4];
                #pragma unroll
                for (int mt = 0; mt < 2; ++mt) {
                    uint32_t off = (uint32_t)(((arow + mt*16) * LDX + ks*16 + kadd) * 2);
                    LDSM_X4(ah[mt][0], ah[mt][1], ah[mt][2], ah[mt][3], xh + off);
                }
                // conflict-free: lane*16 stride within each 512-B j-half block
                const unsigned char* bp0 = sm + OFF_B + (u & 1) * 16384 + k4 * 4096
                                             + ng * 1024 + lane * 16;
                uint4 q0 = *(const uint4*)bp0;           // j0 (x,y), j1 (z,w)
                uint4 q1 = *(const uint4*)(bp0 + 512);   // j2, j3
                MMA_F16(C[0][0], ah[0], q0.x, q0.y);
                MMA_F16(C[1][0], ah[1], q0.x, q0.y);
                MMA_F16(C[0][1], ah[0], q0.z, q0.w);
                MMA_F16(C[1][1], ah[1], q0.z, q0.w);
                MMA_F16(C[0][2], ah[0], q1.x, q1.y);
                MMA_F16(C[1][2], ah[1], q1.x, q1.y);
                MMA_F16(C[0][3], ah[0], q1.z, q1.w);
                MMA_F16(C[1][3], ah[1], q1.z, q1.w);
            }
        }
    };

    // ---- layer-1 pre-mix: X_mixed = A1 @ x gathered from gmem -> fp16 ----
    auto premix_x = [&](int kc) {
        __syncthreads();
        #pragma unroll 1
        for (int idx = tid; idx < MROW * 32; idx += 256) {
            int r = idx >> 5, q = idx & 31;
            float4 s = make_float4(0.f, 0.f, 0.f, 0.f);
            if (r < rows_valid) {
                int n = rown[r];
                const int gbr = b0row + r - n;
                const int base = n * ANN, cnt = Acnt[n];
                for (int e = 0; e < cnt; ++e) {
                    float a = Aw[base + e];
                    const float4 v = __ldg((const float4*)(x + (size_t)(gbr + Ai[base+e]) * 256 + kc*128) + q);
                    s.x = fmaf(a, v.x, s.x); s.y = fmaf(a, v.y, s.y);
                    s.z = fmaf(a, v.z, s.z); s.w = fmaf(a, v.w, s.w);
                }
            }
            *(uint2*)(XH + r*LDX + q*4) = make_uint2(pack_h2(s.x, s.y), pack_h2(s.z, s.w));
        }
        __syncthreads();
    };

    // ---- layers 1/2 epilogue: bias+relu -> XH; then tensor-core mix ----
    auto epi12 = [&](const float* __restrict__ bias, int Lnext) {
        __syncthreads();
        #pragma unroll
        for (int j = 0; j < 4; ++j) {
            int c  = ng*32 + j*8 + (lane&3)*2;
            float2 bb = __ldg((const float2*)(bias + c));
            #pragma unroll
            for (int mt = 0; mt < 2; ++mt) {
                int r0 = m0base + mt*16 + (lane>>2);
                *(uint32_t*)(XH + r0*LDX + c) =
                    pack_h2(fmaxf(C[mt][j][0] + bb.x, 0.f), fmaxf(C[mt][j][1] + bb.y, 0.f));
                *(uint32_t*)(XH + (r0+8)*LDX + c) =
                    pack_h2(fmaxf(C[mt][j][2] + bb.x, 0.f), fmaxf(C[mt][j][3] + bb.y, 0.f));
            }
        }
        __syncthreads();
        ZERO_C();
        #pragma unroll
        for (int ks = 0; ks < 4; ++ks) {
            uint32_t bt[2][4];
            #pragma unroll
            for (int ch = 0; ch < 2; ++ch) {
                uint32_t off = (uint32_t)(((ks*16 + (tmi&1)*8 + trow) * LDX
                                 + ng*32 + ch*16 + (tmi>>1)*8) * 2);
                LDSM_X4_T(bt[ch][0], bt[ch][1], bt[ch][2], bt[ch][3], xh + off);
            }
            #pragma unroll
            for (int mt = 0; mt < 2; ++mt) {
                uint4 p4 = __ldg(&gP[Lnext][mg*2 + mt][ks][lane]);
                uint32_t ap[4] = {p4.x, p4.y, p4.z, p4.w};
                MMA_F16(C[mt][0], ap, bt[0][0], bt[0][1]);
                MMA_F16(C[mt][1], ap, bt[0][2], bt[0][3]);
                MMA_F16(C[mt][2], ap, bt[1][0], bt[1][1]);
                MMA_F16(C[mt][3], ap, bt[1][2], bt[1][3]);
            }
        }
        __syncthreads();
        #pragma unroll
        for (int mt = 0; mt < 2; ++mt)
            #pragma unroll
            for (int j = 0; j < 4; ++j) {
                int c  = ng*32 + j*8 + (lane&3)*2;
                int r0 = m0base + mt*16 + (lane>>2);
                *(uint32_t*)(XH + r0*LDX + c)     = pack_h2(C[mt][j][0], C[mt][j][1]);
                *(uint32_t*)(XH + (r0+8)*LDX + c) = pack_h2(C[mt][j][2], C[mt][j][3]);
            }
    };

    // ================= Layer 1: K=256 (2 pre-mixed chunks) =================
    ZERO_C();
    premix_x(0);
    sweepK(FR_W1,          16);
    premix_x(1);
    sweepK(FR_W1 + 8 * 16, 16);
    epi12(b1, 1);

    // ================= Layer 2: K=128 =================
    ZERO_C();
    sweepK(FR_W2, 16);
    epi12(b2, 2);

    // ================= Layer 3: K=128, N=512 (4 n-chunks), register epi =====
    #pragma unroll 1
    for (int nc = 0; nc < 4; ++nc) {
        ZERO_C();
        sweepK(FR_W3 + nc * 16, 64);
        float facc[12];
        #pragma unroll
        for (int i = 0; i < 12; ++i) facc[i] = 0.f;
        #pragma unroll
        for (int j = 0; j < 4; ++j) {
            int cg = nc*128 + ng*32 + j*8 + (lane&3)*2;
            float2 bb = __ldg((const float2*)(b3 + cg));
            const float4* fp = (const float4*)gFC[nc][ng][j][lane & 3];
            float4 wa = __ldg(fp);       // weights for col cg
            float4 wb = __ldg(fp + 1);   // weights for col cg+1
            #pragma unroll
            for (int mt = 0; mt < 2; ++mt) {
                int r0 = m0base + mt*16 + (lane>>2);
                bool ok0 = (r0     < rows_valid);
                bool ok1 = (r0 + 8 < rows_valid);
                float v00 = ok0 ? fmaxf(C[mt][j][0] + bb.x, 0.f) : 0.f;
                float v01 = ok0 ? fmaxf(C[mt][j][1] + bb.y, 0.f) : 0.f;
                float v10 = ok1 ? fmaxf(C[mt][j][2] + bb.x, 0.f) : 0.f;
                float v11 = ok1 ? fmaxf(C[mt][j][3] + bb.y, 0.f) : 0.f;
                if (ok0) *(float2*)(x3g + (size_t)(b0row + r0    )*512 + cg) = make_float2(v00, v01);
                if (ok1) *(float2*)(x3g + (size_t)(b0row + r0 + 8)*512 + cg) = make_float2(v10, v11);
                facc[(mt*2+0)*3+0] += v00*wa.x + v01*wb.x;
                facc[(mt*2+0)*3+1] += v00*wa.y + v01*wb.y;
                facc[(mt*2+0)*3+2] += v00*wa.z + v01*wb.z;
                facc[(mt*2+1)*3+0] += v10*wa.x + v11*wb.x;
                facc[(mt*2+1)*3+1] += v10*wa.y + v11*wb.y;
                facc[(mt*2+1)*3+2] += v10*wa.z + v11*wb.z;
            }
        }
        #pragma unroll
        for (int i = 0; i < 12; ++i) {
            facc[i] += __shfl_xor_sync(0xFFFFFFFF, facc[i], 1);
            facc[i] += __shfl_xor_sync(0xFFFFFFFF, facc[i], 2);
        }
        if ((lane & 3) == 0) {
            #pragma unroll
            for (int mt = 0; mt < 2; ++mt)
                #pragma unroll
                for (int rh = 0; rh < 2; ++rh) {
                    int r = m0base + mt*16 + (lane>>2) + rh*8;
                    if (r < rows_valid) {
                        #pragma unroll
                        for (int jo = 0; jo < 3; ++jo)
                            atomicAdd(&Oac[r*3 + jo], facc[(mt*2+rh)*3 + jo]);
                    }
                }
        }
    }

    // ---- final out = FC + fcb ----
    __syncthreads();
    if (tid < 189) {
        int r = tid / 3, j = tid - 3*r;
        if (r < rows_valid)
            outg[(size_t)(b0row + r)*3 + j] = Oac[tid] + __ldg(fcb + j);
    }
    #undef ZERO_C
}

extern "C" void kernel_launch(void* const* d_in, const int* in_sizes, int n_in,
                              void* d_out, int out_size) {
    const float* x   = (const float*)d_in[0];
    const float* A1  = (const float*)d_in[1];
    const float* A2  = (const float*)d_in[2];
    const float* A3  = (const float*)d_in[3];
    const float* W1  = (const float*)d_in[4];
    const float* b1  = (const float*)d_in[5];
    const float* W2  = (const float*)d_in[6];
    const float* b2  = (const float*)d_in[7];
    const float* W3  = (const float*)d_in[8];
    const float* b3  = (const float*)d_in[9];
    const float* fcW = (const float*)d_in[10];
    const float* fcb = (const float*)d_in[11];

    const int Btot = in_sizes[0] / (21 * 256);
    float* x3g  = (float*)d_out;
    float* outg = x3g + (size_t)Btot * 21 * 512;

    static int attr_done = 0;
    if (!attr_done) {
        cudaFuncSetAttribute(handnet_mma, cudaFuncAttributeMaxDynamicSharedMemorySize, SMEM_SZ);
        attr_done = 1;
    }

    prep_frags<<<NPREP, 32>>>(W1, W2, W3, A1, A2, A3, fcW);
    const int nCTA = (Btot * 21 + RPC - 1) / RPC;
    handnet_mma<<<nCTA, 256, SMEM_SZ>>>(x, A1, b1, b2, b3, fcb,
                                        x3g, outg, Btot);
}